// round 13
// baseline (speedup 1.0000x reference)
#include <cuda_runtime.h>
#include <cuda_bf16.h>
#include <cstdint>

// f_z[b,i] = z[b,i] + sum_{j<i} h[b, i*(i-1)/2 + j] * z[b,j]
// R13: decouple DRAM depth from registers. Each CTA bulk-async-copies its
// contiguous h spans (8 short rows + 8 long rows, ~16KB) into smem via
// cp.async.bulk + mbarrier (TMA engine drives deep DRAM concurrency), then
// consumes with R11's same-mis row pairing (i, 513-i): z register quads from
// shifted zero-padded smem copies serve every h quad with the lane's own
// registers -- no per-quad z LDS, no shfl in steady state.

#define DIM 512
#define HLEN 130816
#define THREADS 256
#define ZPADF 640
#define FULL 0xffffffffu

#define HA_F 2048        // short-span buffer (max 2012+align words)
#define HB_F 4104        // long-span buffer  (max 4016+align words)
#define HC_F 520         // cg==0 extra span: rows 256,257 (516 words)

struct __align__(16) SmemT {
    float zsh[4 * ZPADF];
    float HA[HA_F];
    float HB[HB_F];
    float HC[HC_F];
    unsigned long long mbar;
};

__device__ __forceinline__ unsigned off_of(int r) {
    return (unsigned)(r * (r - 1) / 2);
}
__device__ __forceinline__ unsigned smem_u32(const void* p) {
    return (unsigned)__cvta_generic_to_shared(p);
}
__device__ __forceinline__ void bulk_g2s(unsigned dst, const float* src,
                                         unsigned bytes, unsigned mb) {
    asm volatile(
        "cp.async.bulk.shared::cta.global.mbarrier::complete_tx::bytes "
        "[%0], [%1], %2, [%3];"
        :: "r"(dst), "l"(src), "r"(bytes), "r"(mb) : "memory");
}
__device__ __forceinline__ void mbar_wait0(unsigned mb) {
    asm volatile(
        "{\n\t.reg .pred P;\n"
        "W_%=:\n\t"
        "mbarrier.try_wait.parity.acquire.cta.shared::cta.b64 P, [%0], 0, 0x989680;\n\t"
        "@P bra D_%=;\n\t"
        "bra W_%=;\n"
        "D_%=:\n\t}"
        :: "r"(mb) : "memory");
}

// ia: short row (2..257), ib: long row (256..511); off(ia)%4 == off(ib)%4 == m.
// ha4/hb4: float4 pointers into smem positioned at the row's aligned-down quad.
__device__ __forceinline__ void do_pair_s(
    const float4* __restrict__ ha4, const float4* __restrict__ hb4,
    int m, int ia, int ib,
    const float* __restrict__ zsh, float* __restrict__ ob, int lane)
{
    const int ea = ia + m, eb = ib + m;        // valid padded elems: [m, e)
    const int nqa = (ea + 3) >> 2;             // <= 65
    const int nqb = (eb + 3) >> 2;             // 64..129
    const int vba = ea >> 2, ca = ea & 3;
    const int vbb = eb >> 2, cb = eb & 3;

    const float4 zf = make_float4(0.f, 0.f, 0.f, 0.f);

    float4 B0 = hb4[lane];                     // nqb >= 64: always valid
    float4 B1 = hb4[lane + 32];
    float4 B2 = (lane + 64  < nqb) ? hb4[lane + 64]  : zf;
    float4 B3 = (lane + 96  < nqb) ? hb4[lane + 96]  : zf;
    float4 B4 = (lane + 128 < nqb) ? hb4[lane + 128] : zf;
    float4 A0 = (lane       < nqa) ? ha4[lane]       : zf;
    float4 A1 = (lane + 32  < nqa) ? ha4[lane + 32]  : zf;
    float4 A2 = (lane + 64  < nqa) ? ha4[lane + 64]  : zf;

    const float4* Zm4 = (const float4*)(zsh + m * ZPADF);
    float4 zq0 = Zm4[lane];
    float4 zq1 = Zm4[lane + 32];
    float4 zq2 = Zm4[lane + 64];
    float4 zq3 = Zm4[lane + 96];
    float4 zq4 = Zm4[lane + 128];

    float s0 = 0.f, s1 = 0.f, s2 = 0.f, s3 = 0.f;
    #define STEP(Q, ZV) {                                       \
        s0 = fmaf(Q.x, ZV.x, s0);                               \
        s1 = fmaf(Q.y, ZV.y, s1);                               \
        s2 = fmaf(Q.z, ZV.z, s2);                               \
        s3 = fmaf(Q.w, ZV.w, s3);                               \
    }
    STEP(B0, zq0) STEP(B1, zq1) STEP(B2, zq2)
    STEP(B3, zq3) STEP(B4, zq4)
    float sumb = (s0 + s1) + (s2 + s3);

    s0 = s1 = s2 = s3 = 0.f;
    STEP(A0, zq0) STEP(A1, zq1) STEP(A2, zq2)
    float suma = (s0 + s1) + (s2 + s3);
    #undef STEP

    // tail-junk subtract (components k >= c of boundary quad), all regs
    if (cb && lane == (vbb & 31)) {            // vbb>>5 in {2,3,4}
        const int st = vbb >> 5;
        float4 Q  = (st == 2) ? B2  : (st == 3) ? B3  : B4;
        float4 zt = (st == 2) ? zq2 : (st == 3) ? zq3 : zq4;
        float jnk = Q.w * zt.w;
        if (cb <= 2) jnk = fmaf(Q.z, zt.z, jnk);
        if (cb <= 1) jnk = fmaf(Q.y, zt.y, jnk);
        sumb -= jnk;
    }
    if (ca && lane == (vba & 31)) {            // vba>>5 in {0,1,2}
        const int st = vba >> 5;
        float4 Q  = (st == 0) ? A0  : (st == 1) ? A1  : A2;
        float4 zt = (st == 0) ? zq0 : (st == 1) ? zq1 : zq2;
        float jnk = Q.w * zt.w;
        if (ca <= 2) jnk = fmaf(Q.z, zt.z, jnk);
        if (ca <= 1) jnk = fmaf(Q.y, zt.y, jnk);
        suma -= jnk;
    }

    #pragma unroll
    for (int o = 16; o; o >>= 1) {
        suma += __shfl_xor_sync(FULL, suma, o);
        sumb += __shfl_xor_sync(FULL, sumb, o);
    }

    if (lane == 0) {
        ob[ia] = zsh[ia] + suma;               // Z_0 is plain z
        ob[ib] = zsh[ib] + sumb;
    }
}

__global__ __launch_bounds__(THREADS) void LinearMap_kernel(
    const float* __restrict__ z,
    const float* __restrict__ h,
    float* __restrict__ out,
    int out_size)
{
    __shared__ SmemT sm;

    const int b    = blockIdx.x >> 5;   // 32 groups per batch
    const int cg   = blockIdx.x & 31;
    const int tid  = threadIdx.x;
    const int warp = tid >> 5;
    const int lane = tid & 31;

    // ---- span computation (word indices into this batch's h) ----
    const unsigned sS = off_of(8 * cg);
    const unsigned eS = off_of(8 * cg + 8);
    unsigned sL, eL;
    if (cg == 0) { sL = off_of(506);          eL = HLEN; }
    else         { sL = off_of(506 - 8 * cg); eL = off_of(514 - 8 * cg); }
    const unsigned sSa = sS & ~3u, eSa = (eS + 3u) & ~3u;
    const unsigned sLa = sL & ~3u, eLa = (eL + 3u) & ~3u;

    const float* hbat = h + (size_t)b * HLEN;

    const unsigned mb = smem_u32(&sm.mbar);
    if (tid == 0) {
        asm volatile("mbarrier.init.shared.b64 [%0], 1;" :: "r"(mb) : "memory");
    }
    __syncthreads();

    if (tid == 0) {
        const unsigned bytesA = (eSa - sSa) * 4u;
        const unsigned bytesB = (eLa - sLa) * 4u;
        const unsigned bytesC = (cg == 0) ? 2064u : 0u;   // words [32640,33156)
        asm volatile("mbarrier.arrive.expect_tx.shared.b64 _, [%0], %1;"
                     :: "r"(mb), "r"(bytesA + bytesB + bytesC) : "memory");
        bulk_g2s(smem_u32(sm.HA), hbat + sSa, bytesA, mb);
        bulk_g2s(smem_u32(sm.HB), hbat + sLa, bytesB, mb);
        if (cg == 0) bulk_g2s(smem_u32(sm.HC), hbat + 32640, bytesC, mb);
    }

    // ---- z fill (overlaps the bulk copies) ----
    {
        int m = tid >> 6;                      // 0..3: zero pads
        int j = 512 + (tid & 63);
        sm.zsh[m * ZPADF + j]      = 0.f;
        sm.zsh[m * ZPADF + j + 64] = 0.f;
        if (tid < 16) {
            int mm = tid >> 2, k = tid & 3;
            if (k < mm) sm.zsh[mm * ZPADF + k] = 0.f;
        }
    }
    __syncthreads();
    {
        const float* zb = z + (size_t)b * DIM;
        #pragma unroll
        for (int j = tid; j < DIM; j += THREADS) {
            float v = zb[j];
            sm.zsh[j]                 = v;
            sm.zsh[ZPADF     + j + 1] = v;
            sm.zsh[2 * ZPADF + j + 2] = v;
            sm.zsh[3 * ZPADF + j + 3] = v;
        }
    }
    __syncthreads();

    // ---- wait for h tiles ----
    mbar_wait0(mb);

    // ---- consume: one work unit per warp ----
    float* ob = out + (size_t)b * DIM;
    const int w = 8 * cg + warp;
    if (w >= 2) {
        const int ia = w, ib = 513 - w;
        const unsigned offa = off_of(ia), offb = off_of(ib);
        const int m = (int)(offa & 3u);
        const float4* ha4 = (const float4*)&sm.HA[(offa & ~3u) - sSa];
        const float4* hb4 = (const float4*)&sm.HB[(offb & ~3u) - sLa];
        do_pair_s(ha4, hb4, m, ia, ib, sm.zsh, ob, lane);
    } else if (w == 1) {                       // rows 257, 256 (both mis 0)
        const float4* ha4 = (const float4*)&sm.HC[off_of(257) - 32640]; // +256
        const float4* hb4 = (const float4*)&sm.HC[0];
        do_pair_s(ha4, hb4, 0, 257, 256, sm.zsh, ob, lane);
    } else if (lane == 0) {                    // rows 0, 1 (cg==0, sSa==0)
        ob[0] = sm.zsh[0];
        ob[1] = sm.zsh[1] + sm.HA[0] * sm.zsh[0];
    }

    // logdet / tail zeroing (d_out is poisoned)
    if (blockIdx.x == 0) {
        const int nfz = (int)(gridDim.x >> 5) * DIM;
        for (int k = nfz + tid; k < out_size; k += THREADS) out[k] = 0.0f;
    }
}

extern "C" void kernel_launch(void* const* d_in, const int* in_sizes, int n_in,
                              void* d_out, int out_size)
{
    const float* z = (const float*)d_in[0];   // [batch, 512]
    const float* h = (const float*)d_in[1];   // [batch, 130816]
    float* out = (float*)d_out;

    const int batch = in_sizes[0] / DIM;      // 256

    dim3 grid(batch * 32);                    // 8192 CTAs, 8 pairs each
    LinearMap_kernel<<<grid, THREADS>>>(z, h, out, out_size);
}

// round 14
// speedup vs baseline: 1.2913x; 1.2913x over previous
#include <cuda_runtime.h>
#include <cuda_bf16.h>
#include <cstdint>

// f_z[b,i] = z[b,i] + sum_{j<i} h[b, i*(i-1)/2 + j] * z[b,j]
// Trunk = R11: pair rows (i, 513-i) -> same off%4 class m, so z register
// quads (from shifted zero-padded smem copies Z_m) serve every h quad with
// the lane's own regs; no per-quad LDS, no shfl in steady state.
// R14: hoist pair-1's 8 predicated LDG.128 ABOVE the z-fill + syncthreads
// (h loads are z-independent) so DRAM latency overlaps the fill; 2 work
// units per warp keep the pipe primed across the reduce.

#define DIM 512
#define HLEN 130816
#define THREADS 256
#define ZPADF 640
#define FULL 0xffffffffu

__device__ __forceinline__ unsigned off_of(int r) {
    return (unsigned)(r * (r - 1) / 2);
}

struct HQ {
    float4 B0, B1, B2, B3, B4, A0, A1, A2;
    int m, ea, eb, nqa, nqb;
};

// map work unit w (0..255 per batch) to a same-mis row pair
__device__ __forceinline__ void map_unit(int w, int& ia, int& ib) {
    if (w >= 2)      { ia = w;   ib = 513 - w; }
    else             { ia = 257; ib = 256;     }   // w==1 (w==0 inactive)
}

__device__ __forceinline__ void hq_load(const float* __restrict__ hbase,
                                        int ia, int ib, int lane, bool active,
                                        HQ& X)
{
    const unsigned offa = off_of(ia);
    const unsigned offb = off_of(ib);
    X.m  = (int)(offa & 3u);
    X.ea = ia + X.m;
    X.eb = ib + X.m;
    X.nqa = active ? ((X.ea + 3) >> 2) : 0;    // <= 65
    X.nqb = active ? ((X.eb + 3) >> 2) : 0;    // 64..129 when active

    const float4* ha4 = (const float4*)(hbase + (offa & ~3u));
    const float4* hb4 = (const float4*)(hbase + (offb & ~3u));
    const float4 zf = make_float4(0.f, 0.f, 0.f, 0.f);

    X.B0 = (lane       < X.nqb) ? __ldcs(hb4 + lane)       : zf;
    X.B1 = (lane + 32  < X.nqb) ? __ldcs(hb4 + lane + 32)  : zf;
    X.B2 = (lane + 64  < X.nqb) ? __ldcs(hb4 + lane + 64)  : zf;
    X.B3 = (lane + 96  < X.nqb) ? __ldcs(hb4 + lane + 96)  : zf;
    X.B4 = (lane + 128 < X.nqb) ? __ldcs(hb4 + lane + 128) : zf;
    X.A0 = (lane       < X.nqa) ? __ldcs(ha4 + lane)       : zf;
    X.A1 = (lane + 32  < X.nqa) ? __ldcs(ha4 + lane + 32)  : zf;
    X.A2 = (lane + 64  < X.nqa) ? __ldcs(ha4 + lane + 64)  : zf;
}

__device__ __forceinline__ void hq_consume(const HQ& X,
                                           const float* __restrict__ zsh,
                                           float* __restrict__ ob,
                                           int ia, int ib, int lane)
{
    const int vba = X.ea >> 2, ca = X.ea & 3;
    const int vbb = X.eb >> 2, cb = X.eb & 3;

    const float4* Zm4 = (const float4*)(zsh + X.m * ZPADF);
    float4 zq0 = Zm4[lane];
    float4 zq1 = Zm4[lane + 32];
    float4 zq2 = Zm4[lane + 64];
    float4 zq3 = Zm4[lane + 96];
    float4 zq4 = Zm4[lane + 128];

    float s0 = 0.f, s1 = 0.f, s2 = 0.f, s3 = 0.f;
    #define STEP(Q, ZV) {                                       \
        s0 = fmaf(Q.x, ZV.x, s0);                               \
        s1 = fmaf(Q.y, ZV.y, s1);                               \
        s2 = fmaf(Q.z, ZV.z, s2);                               \
        s3 = fmaf(Q.w, ZV.w, s3);                               \
    }
    STEP(X.B0, zq0) STEP(X.B1, zq1) STEP(X.B2, zq2)
    STEP(X.B3, zq3) STEP(X.B4, zq4)
    float sumb = (s0 + s1) + (s2 + s3);

    s0 = s1 = s2 = s3 = 0.f;
    STEP(X.A0, zq0) STEP(X.A1, zq1) STEP(X.A2, zq2)
    float suma = (s0 + s1) + (s2 + s3);
    #undef STEP

    // tail-junk subtract (components k >= c of boundary quad), all regs
    if (cb && lane == (vbb & 31)) {            // vbb>>5 in {2,3,4}
        const int st = vbb >> 5;
        float4 Q  = (st == 2) ? X.B2 : (st == 3) ? X.B3 : X.B4;
        float4 zt = (st == 2) ? zq2  : (st == 3) ? zq3  : zq4;
        float jnk = Q.w * zt.w;
        if (cb <= 2) jnk = fmaf(Q.z, zt.z, jnk);
        if (cb <= 1) jnk = fmaf(Q.y, zt.y, jnk);
        sumb -= jnk;
    }
    if (ca && lane == (vba & 31)) {            // vba>>5 in {0,1,2}
        const int st = vba >> 5;
        float4 Q  = (st == 0) ? X.A0 : (st == 1) ? X.A1 : X.A2;
        float4 zt = (st == 0) ? zq0  : (st == 1) ? zq1  : zq2;
        float jnk = Q.w * zt.w;
        if (ca <= 2) jnk = fmaf(Q.z, zt.z, jnk);
        if (ca <= 1) jnk = fmaf(Q.y, zt.y, jnk);
        suma -= jnk;
    }

    #pragma unroll
    for (int o = 16; o; o >>= 1) {
        suma += __shfl_xor_sync(FULL, suma, o);
        sumb += __shfl_xor_sync(FULL, sumb, o);
    }

    if (lane == 0) {
        ob[ia] = zsh[ia] + suma;               // Z_0 is plain z
        ob[ib] = zsh[ib] + sumb;
    }
}

__global__ __launch_bounds__(THREADS, 4) void LinearMap_kernel(
    const float* __restrict__ z,
    const float* __restrict__ h,
    float* __restrict__ out,
    int out_size)
{
    __shared__ float zsh[4 * ZPADF];    // shifted copy m at m*ZPADF

    const int b    = blockIdx.x >> 4;   // / 16
    const int cg   = blockIdx.x & 15;
    const int tid  = threadIdx.x;
    const int warp = tid >> 5;
    const int lane = tid & 31;

    const float* hbase = h + (size_t)b * HLEN;
    const int base = cg * 16;
    const int w1 = base + warp;
    const int w2 = base + 8 + warp;     // always >= 8 (generic pair)

    // ---- hoisted pair-1 loads: in flight during z-fill ----
    int ia1, ib1; map_unit(w1, ia1, ib1);
    HQ X;
    hq_load(hbase, ia1, ib1, lane, w1 >= 1, X);

    // ---- z fill (overlaps pair-1 DRAM latency) ----
    {
        int m = tid >> 6;               // zero pads: [512,640) + heads [0,m)
        int j = 512 + (tid & 63);
        zsh[m * ZPADF + j]      = 0.f;
        zsh[m * ZPADF + j + 64] = 0.f;
        if (tid < 16) {
            int mm = tid >> 2, k = tid & 3;
            if (k < mm) zsh[mm * ZPADF + k] = 0.f;
        }
    }
    __syncthreads();
    {
        const float* zb = z + (size_t)b * DIM;
        #pragma unroll
        for (int j = tid; j < DIM; j += THREADS) {
            float v = zb[j];
            zsh[j]                 = v;
            zsh[ZPADF     + j + 1] = v;
            zsh[2 * ZPADF + j + 2] = v;
            zsh[3 * ZPADF + j + 3] = v;
        }
    }
    __syncthreads();

    float* ob = out + (size_t)b * DIM;

    // ---- consume pair 1 ----
    if (w1 >= 1) hq_consume(X, zsh, ob, ia1, ib1, lane);
    else if (lane == 0) {                      // w1==0: rows 0, 1
        ob[0] = zsh[0];
        ob[1] = zsh[1] + hbase[0] * zsh[0];
    }

    // ---- pair 2: load (regs reused) + consume ----
    int ia2, ib2; map_unit(w2, ia2, ib2);
    HQ Y;
    hq_load(hbase, ia2, ib2, lane, true, Y);
    hq_consume(Y, zsh, ob, ia2, ib2, lane);

    // logdet / tail zeroing (d_out is poisoned)
    if (blockIdx.x == 0) {
        const int nfz = (int)(gridDim.x >> 4) * DIM;
        for (int k = nfz + tid; k < out_size; k += THREADS) out[k] = 0.0f;
    }
}

extern "C" void kernel_launch(void* const* d_in, const int* in_sizes, int n_in,
                              void* d_out, int out_size)
{
    const float* z = (const float*)d_in[0];   // [batch, 512]
    const float* h = (const float*)d_in[1];   // [batch, 130816]
    float* out = (float*)d_out;

    const int batch = in_sizes[0] / DIM;      // 256

    dim3 grid(batch * 16);                    // 4096 identical CTAs
    LinearMap_kernel<<<grid, THREADS>>>(z, h, out, out_size);
}